// round 11
// baseline (speedup 1.0000x reference)
#include <cuda_runtime.h>
#include <math.h>

typedef unsigned long long ull;

#define NROWS 262144

// ---------------- device scratch ----------------
__device__ float  g_cnorm[1024];
__device__ int    g_counts[1024];
__device__ double g_loss;
__device__ float  g_ze[(size_t)NROWS * 64];
__device__ int    g_idx[NROWS];
__device__ float  g_table[1024 * 9];

// ---------------- packed f32x2 helpers ----------------
__device__ __forceinline__ void fma2(ull &d, ull a, ull b) {
    asm("fma.rn.f32x2 %0, %1, %2, %0;" : "+l"(d) : "l"(a), "l"(b));
}
__device__ __forceinline__ ull pk2(float lo, float hi) {
    ull r; asm("mov.b64 %0, {%1, %2};" : "=l"(r) : "f"(lo), "f"(hi)); return r;
}
__device__ __forceinline__ float upk_sum(ull v) {
    float lo, hi; asm("mov.b64 {%0, %1}, %2;" : "=f"(lo), "=f"(hi) : "l"(v));
    return lo + hi;
}

// ======================= init =======================
__global__ void vq_init_kernel(const float* __restrict__ cb) {
    int j = blockIdx.x * blockDim.x + threadIdx.x;
    if (j < 1024) {
        float sum = 0.f;
        #pragma unroll
        for (int k = 0; k < 64; k += 4) {
            float4 v = *reinterpret_cast<const float4*>(&cb[j*64 + k]);
            sum = fmaf(v.x,v.x, fmaf(v.y,v.y, fmaf(v.z,v.z, fmaf(v.w,v.w, sum))));
        }
        g_cnorm[j]  = sum;
        g_counts[j] = 0;
        if (j == 0) g_loss = 0.0;
    }
}

// ======================= encoder (512 threads) =======================
#define E_W2 0
#define E_B2 33280
#define E_W3 33408
#define E_B3 41856
#define E_XS 41920
#define E_H1 42240
#define E_H2 50432
#define E_TOTAL 54656
#define ENT 512

__global__ void __launch_bounds__(ENT, 1) vq_enc_kernel(
    const float* __restrict__ x,
    const float* __restrict__ w1, const float* __restrict__ b1,
    const float* __restrict__ w2, const float* __restrict__ b2,
    const float* __restrict__ w3, const float* __restrict__ b3)
{
    extern __shared__ float s[];
    const int tid = threadIdx.x;

    for (int i = tid; i < 128*256; i += ENT) { int r = i >> 8, c = i & 255; s[E_W2 + r*260 + c] = w2[i]; }
    for (int i = tid; i < 128;     i += ENT) s[E_B2 + i] = b2[i];
    for (int i = tid; i < 64*128;  i += ENT) { int r = i >> 7, c = i & 127; s[E_W3 + r*132 + c] = w3[i]; }
    for (int i = tid; i < 64;      i += ENT) s[E_B3 + i] = b3[i];

    const int col1 = tid & 255;
    const int rp0  = (tid >> 8) * 8;
    ull rw1p[9];
    const float rb1 = __ldg(&b1[col1]);
    #pragma unroll
    for (int k = 0; k < 9; k++) { float w = __ldg(&w1[col1*9 + k]); rw1p[k] = pk2(w, w); }
    __syncthreads();

    const int cp  = tid & 63, rg  = tid >> 6;
    const int cq  = tid & 31, rg3 = tid >> 5;

    for (int tile = blockIdx.x; tile < NROWS/32; tile += gridDim.x) {
        const int row0 = tile * 32;

        if (tid < 288) {
            int r = tid / 9, k = tid - r*9;
            s[E_XS + k*32 + r] = x[(size_t)(row0 + r)*9 + k];
        }
        __syncthreads();

        // L1: 9 -> 256, relu
        #pragma unroll
        for (int j = 0; j < 8; j++) {
            const int rp = rp0 + j;
            ull acc = pk2(rb1, rb1);
            #pragma unroll
            for (int k = 0; k < 9; k++)
                fma2(acc, *reinterpret_cast<const ull*>(&s[E_XS + k*32 + 2*rp]), rw1p[k]);
            float lo, hi; asm("mov.b64 {%0,%1}, %2;" : "=f"(lo), "=f"(hi) : "l"(acc));
            s[E_H1 + (2*rp)  *256 + col1] = fmaxf(lo, 0.f);
            s[E_H1 + (2*rp+1)*256 + col1] = fmaxf(hi, 0.f);
        }
        __syncthreads();

        // L2: 256 -> 128, relu (2 cols x 4 rows)
        {
            ull acc[4][2];
            const float bb0 = s[E_B2 + cp], bb1 = s[E_B2 + cp + 64];
            #pragma unroll
            for (int i = 0; i < 4; i++) { acc[i][0] = pk2(bb0, 0.f); acc[i][1] = pk2(bb1, 0.f); }
            const float* w0p = &s[E_W2 + cp*260];
            const float* w1p = &s[E_W2 + (cp+64)*260];
            const float* hp  = &s[E_H1 + rg*4*256];
            #pragma unroll 4
            for (int k4 = 0; k4 < 256; k4 += 4) {
                ulonglong2 w0  = *reinterpret_cast<const ulonglong2*>(w0p + k4);
                ulonglong2 w1v = *reinterpret_cast<const ulonglong2*>(w1p + k4);
                #pragma unroll
                for (int i = 0; i < 4; i++) {
                    ulonglong2 h = *reinterpret_cast<const ulonglong2*>(hp + i*256 + k4);
                    fma2(acc[i][0], w0.x,  h.x); fma2(acc[i][0], w0.y,  h.y);
                    fma2(acc[i][1], w1v.x, h.x); fma2(acc[i][1], w1v.y, h.y);
                }
            }
            #pragma unroll
            for (int i = 0; i < 4; i++) {
                s[E_H2 + (rg*4+i)*132 + cp]      = fmaxf(upk_sum(acc[i][0]), 0.f);
                s[E_H2 + (rg*4+i)*132 + cp + 64] = fmaxf(upk_sum(acc[i][1]), 0.f);
            }
        }
        __syncthreads();

        // L3: 128 -> 64 (2 cols x 2 rows)
        {
            ull acc[2][2];
            const float bb0 = s[E_B3 + cq], bb1 = s[E_B3 + cq + 32];
            #pragma unroll
            for (int i = 0; i < 2; i++) { acc[i][0] = pk2(bb0, 0.f); acc[i][1] = pk2(bb1, 0.f); }
            const float* w0p = &s[E_W3 + cq*132];
            const float* w1p = &s[E_W3 + (cq+32)*132];
            const float* hp  = &s[E_H2 + rg3*2*132];
            #pragma unroll 4
            for (int k4 = 0; k4 < 128; k4 += 4) {
                ulonglong2 w0  = *reinterpret_cast<const ulonglong2*>(w0p + k4);
                ulonglong2 w1v = *reinterpret_cast<const ulonglong2*>(w1p + k4);
                #pragma unroll
                for (int i = 0; i < 2; i++) {
                    ulonglong2 h = *reinterpret_cast<const ulonglong2*>(hp + i*132 + k4);
                    fma2(acc[i][0], w0.x,  h.x); fma2(acc[i][0], w0.y,  h.y);
                    fma2(acc[i][1], w1v.x, h.x); fma2(acc[i][1], w1v.y, h.y);
                }
            }
            #pragma unroll
            for (int i = 0; i < 2; i++) {
                size_t row = (size_t)(row0 + rg3*2 + i);
                g_ze[row*64 + cq]      = upk_sum(acc[i][0]);
                g_ze[row*64 + cq + 32] = upk_sum(acc[i][1]);
            }
        }
        __syncthreads();
    }
}

// ======================= distance / argmin / loss / hist =======================
// R7 layout (stride-70 codebook tile, norms at col 64), 3 CTAs/SM target.
#define D_ZS 0
#define D_CB 8704
#define D_SB 17664
#define D_SI 17792
#define D_ZN 17920
#define D_LR 18048
#define D_TOTAL 18056
#define DNT 256

__global__ void __launch_bounds__(DNT, 3) vq_dist_kernel(const float* __restrict__ cb)
{
    extern __shared__ float s[];
    const int tid  = threadIdx.x;
    const int lane = tid & 31, warp = tid >> 5;
    const int r0 = warp * 16;

    for (int st = blockIdx.x; st < NROWS/128; st += gridDim.x) {
        const size_t base = (size_t)st * 128 * 64;

        for (int i = tid; i < 2048; i += DNT) {
            float4 v = *reinterpret_cast<const float4*>(&g_ze[base + (size_t)i*4]);
            int r = i >> 4, c4 = (i & 15) * 4;
            *reinterpret_cast<float4*>(&s[D_ZS + r*68 + c4]) = v;
        }
        __syncthreads();

        if (tid < 128) {
            float zn = 0.f;
            const float* zp = &s[D_ZS + tid*68];
            #pragma unroll
            for (int k = 0; k < 64; k += 4) {
                float4 v = *reinterpret_cast<const float4*>(zp + k);
                zn = fmaf(v.x,v.x, fmaf(v.y,v.y, fmaf(v.z,v.z, fmaf(v.w,v.w, zn))));
            }
            s[D_ZN + tid] = zn;
        }

        // per-lane running argmin: best[16] floats + u16-packed indices (reg-lean)
        float best[16];
        unsigned bidx16[8];
        #pragma unroll
        for (int i = 0; i < 16; i++) best[i] = 1e30f;
        #pragma unroll
        for (int i = 0; i < 8; i++) bidx16[i] = 0u;
        __syncthreads();

        for (int p = 0; p < 8; p++) {
            const int cbase = p * 128;
            for (int i = tid; i < 2048; i += DNT) {
                int r = i >> 4, q4 = (i & 15) * 4;
                ulonglong2 v = *reinterpret_cast<const ulonglong2*>(&cb[(size_t)(cbase + r)*64 + q4]);
                *reinterpret_cast<ull*>(&s[D_CB + r*70 + q4])     = v.x;
                *reinterpret_cast<ull*>(&s[D_CB + r*70 + q4 + 2]) = v.y;
            }
            if (tid < 128) s[D_CB + tid*70 + 64] = g_cnorm[cbase + tid];
            __syncthreads();

            #pragma unroll 1
            for (int cc = 0; cc < 2; cc++) {
                const int c0 = cc*64 + lane, c1 = c0 + 32;
                const float* b0p = &s[D_CB + c0*70];
                const float* b1p = &s[D_CB + c1*70];
                const float cn0 = b0p[64], cn1 = b1p[64];
                const int j0 = cbase + c0, j1 = cbase + c1;
                #pragma unroll 1
                for (int rp = 0; rp < 2; rp++) {
                    ull acc0[8], acc1[8];
                    #pragma unroll
                    for (int i = 0; i < 8; i++) { acc0[i] = 0ull; acc1[i] = 0ull; }
                    const float* ap = &s[D_ZS + (r0 + rp*8)*68];
                    #pragma unroll 2
                    for (int k4 = 0; k4 < 64; k4 += 4) {
                        // stride-70 rows are only 8B-aligned: must stay ull (8B) loads
                        ull b00 = *reinterpret_cast<const ull*>(b0p + k4);
                        ull b01 = *reinterpret_cast<const ull*>(b0p + k4 + 2);
                        ull b10 = *reinterpret_cast<const ull*>(b1p + k4);
                        ull b11 = *reinterpret_cast<const ull*>(b1p + k4 + 2);
                        #pragma unroll
                        for (int i = 0; i < 8; i++) {
                            ulonglong2 a = *reinterpret_cast<const ulonglong2*>(ap + i*68 + k4);
                            fma2(acc0[i], b00, a.x); fma2(acc0[i], b01, a.y);
                            fma2(acc1[i], b10, a.x); fma2(acc1[i], b11, a.y);
                        }
                    }
                    #pragma unroll
                    for (int i = 0; i < 8; i++) {
                        const int row = rp*8 + i;
                        float d0 = fmaf(-2.f, upk_sum(acc0[i]), cn0);
                        float d1 = fmaf(-2.f, upk_sum(acc1[i]), cn1);
                        // within-lane candidates visited in ascending index order; strict < keeps lowest
                        if (d0 < best[row]) {
                            best[row] = d0;
                            if (row & 1) bidx16[row>>1] = (bidx16[row>>1] & 0x0000FFFFu) | ((unsigned)j0 << 16);
                            else         bidx16[row>>1] = (bidx16[row>>1] & 0xFFFF0000u) | (unsigned)j0;
                        }
                        if (d1 < best[row]) {
                            best[row] = d1;
                            if (row & 1) bidx16[row>>1] = (bidx16[row>>1] & 0x0000FFFFu) | ((unsigned)j1 << 16);
                            else         bidx16[row>>1] = (bidx16[row>>1] & 0xFFFF0000u) | (unsigned)j1;
                        }
                    }
                }
            }
            __syncthreads();
        }

        // cross-lane argmin, once per tile (tie-break: smaller index)
        #pragma unroll
        for (int i = 0; i < 16; i++) {
            float v = best[i];
            int id = (int)((bidx16[i>>1] >> (16 * (i & 1))) & 0xFFFFu);
            #pragma unroll
            for (int off = 16; off; off >>= 1) {
                float ov = __shfl_down_sync(0xffffffffu, v, off);
                int   oi = __shfl_down_sync(0xffffffffu, id, off);
                if (ov < v || (ov == v && oi < id)) { v = ov; id = oi; }
            }
            if (lane == 0) {
                s[D_SB + r0 + i] = v;
                reinterpret_cast<int*>(&s[D_SI])[r0 + i] = id;
            }
        }
        __syncthreads();

        float ll = 0.f;
        if (tid < 128) {
            int id = reinterpret_cast<int*>(&s[D_SI])[tid];
            ll = s[D_SB + tid] + s[D_ZN + tid];
            g_idx[st*128 + tid] = id;
            atomicAdd(&g_counts[id], 1);
        }
        #pragma unroll
        for (int off = 16; off; off >>= 1) ll += __shfl_down_sync(0xffffffffu, ll, off);
        if (lane == 0) s[D_LR + warp] = ll;
        __syncthreads();
        if (tid == 0) {
            float tot = 0.f;
            #pragma unroll
            for (int w = 0; w < 8; w++) tot += s[D_LR + w];
            atomicAdd(&g_loss, (double)tot);
        }
        __syncthreads();
    }
}

// ======================= decoder table: mlp3 over the 1024 codebook rows =======================
#define C_W1  0
#define C_B1  8704
#define C_W2  8832
#define C_B2  42624
#define C_W3  42880
#define C_B3  45220
#define C_S1  45232
#define C_S2  53552
#define C_TOTAL 57808
#define CNT 256

__global__ void __launch_bounds__(CNT, 1) vq_dectab_kernel(
    const float* __restrict__ w1, const float* __restrict__ b1,
    const float* __restrict__ w2, const float* __restrict__ b2,
    const float* __restrict__ w3, const float* __restrict__ b3,
    const float* __restrict__ cb)
{
    extern __shared__ float s[];
    const int tid = threadIdx.x;

    for (int i = tid; i < 128*64;  i += CNT) { int r = i >> 6, c = i & 63;  s[C_W1 + r*68  + c] = w1[i]; }
    for (int i = tid; i < 128;     i += CNT) s[C_B1 + i] = b1[i];
    for (int i = tid; i < 256*128; i += CNT) { int r = i >> 7, c = i & 127; s[C_W2 + r*132 + c] = w2[i]; }
    for (int i = tid; i < 256;     i += CNT) s[C_B2 + i] = b2[i];
    for (int i = tid; i < 9*256;   i += CNT) { int r = i >> 8, c = i & 255; s[C_W3 + r*260 + c] = w3[i]; }
    for (int i = tid; i < 9;       i += CNT) s[C_B3 + i] = b3[i];
    __syncthreads();

    const int cp = tid & 63, rg = tid >> 6;

    for (int tile = blockIdx.x; tile < 1024/32; tile += gridDim.x) {
        const int row0 = tile * 32;

        for (int t = tid; t < 512; t += CNT) {
            int r = t >> 4, j = (t & 15) * 4;
            float4 v = *reinterpret_cast<const float4*>(&cb[(size_t)(row0 + r)*64 + j]);
            *reinterpret_cast<float4*>(&s[C_S1 + r*68 + j]) = v;
        }
        __syncthreads();

        // D1: 64 -> 128, relu (2 cols x 8 rows)
        {
            ull acc[8][2];
            const float bb0 = s[C_B1 + cp], bb1 = s[C_B1 + cp + 64];
            #pragma unroll
            for (int i = 0; i < 8; i++) { acc[i][0] = pk2(bb0, 0.f); acc[i][1] = pk2(bb1, 0.f); }
            const float* w0p = &s[C_W1 + cp*68];
            const float* w1p = &s[C_W1 + (cp+64)*68];
            const float* hp  = &s[C_S1 + rg*8*68];
            #pragma unroll 4
            for (int k4 = 0; k4 < 64; k4 += 4) {
                ulonglong2 w0  = *reinterpret_cast<const ulonglong2*>(w0p + k4);
                ulonglong2 w1v = *reinterpret_cast<const ulonglong2*>(w1p + k4);
                #pragma unroll
                for (int i = 0; i < 8; i++) {
                    ulonglong2 h = *reinterpret_cast<const ulonglong2*>(hp + i*68 + k4);
                    fma2(acc[i][0], w0.x,  h.x); fma2(acc[i][0], w0.y,  h.y);
                    fma2(acc[i][1], w1v.x, h.x); fma2(acc[i][1], w1v.y, h.y);
                }
            }
            #pragma unroll
            for (int i = 0; i < 8; i++) {
                s[C_S2 + (rg*8+i)*132 + cp]      = fmaxf(upk_sum(acc[i][0]), 0.f);
                s[C_S2 + (rg*8+i)*132 + cp + 64] = fmaxf(upk_sum(acc[i][1]), 0.f);
            }
        }
        __syncthreads();

        // D2: 128 -> 256, relu (4 cols x 8 rows)
        {
            ull acc[8][4];
            #pragma unroll
            for (int c = 0; c < 4; c++) {
                const float bb = s[C_B2 + cp + 64*c];
                #pragma unroll
                for (int i = 0; i < 8; i++) acc[i][c] = pk2(bb, 0.f);
            }
            const float* wp0 = &s[C_W2 + cp*132];
            const float* wp1 = &s[C_W2 + (cp+64)*132];
            const float* wp2 = &s[C_W2 + (cp+128)*132];
            const float* wp3 = &s[C_W2 + (cp+192)*132];
            const float* hp  = &s[C_S2 + rg*8*132];
            #pragma unroll 2
            for (int k4 = 0; k4 < 128; k4 += 4) {
                ulonglong2 w0 = *reinterpret_cast<const ulonglong2*>(wp0 + k4);
                ulonglong2 w1 = *reinterpret_cast<const ulonglong2*>(wp1 + k4);
                ulonglong2 w2 = *reinterpret_cast<const ulonglong2*>(wp2 + k4);
                ulonglong2 w3 = *reinterpret_cast<const ulonglong2*>(wp3 + k4);
                #pragma unroll
                for (int i = 0; i < 8; i++) {
                    ulonglong2 h = *reinterpret_cast<const ulonglong2*>(hp + i*132 + k4);
                    fma2(acc[i][0], w0.x, h.x); fma2(acc[i][0], w0.y, h.y);
                    fma2(acc[i][1], w1.x, h.x); fma2(acc[i][1], w1.y, h.y);
                    fma2(acc[i][2], w2.x, h.x); fma2(acc[i][2], w2.y, h.y);
                    fma2(acc[i][3], w3.x, h.x); fma2(acc[i][3], w3.y, h.y);
                }
            }
            #pragma unroll
            for (int i = 0; i < 8; i++)
                #pragma unroll
                for (int c = 0; c < 4; c++)
                    s[C_S1 + (rg*8+i)*260 + cp + 64*c] = fmaxf(upk_sum(acc[i][c]), 0.f);
        }
        __syncthreads();

        // D3: 256 -> 9, to table
        for (int t = tid; t < 288; t += CNT) {
            int r = t / 9, c = t - r*9;
            ull a0 = pk2(s[C_B3 + c], 0.f), a1 = 0ull;
            const float* wp  = &s[C_W3 + c*260];
            const float* hp2 = &s[C_S1 + r*260];
            #pragma unroll 4
            for (int k4 = 0; k4 < 256; k4 += 4) {
                ulonglong2 w = *reinterpret_cast<const ulonglong2*>(wp + k4);
                ulonglong2 h = *reinterpret_cast<const ulonglong2*>(hp2 + k4);
                fma2(a0, w.x, h.x); fma2(a1, w.y, h.y);
            }
            g_table[(row0 + r)*9 + c] = upk_sum(a0) + upk_sum(a1);
        }
        __syncthreads();
    }
}

// ======================= gather: out[i] = table[idx[i]] =======================
__global__ void vq_gather_kernel(float* __restrict__ out) {
    const int e = blockIdx.x * blockDim.x + threadIdx.x;   // over NROWS*9
    if (e < NROWS * 9) {
        const unsigned row = (unsigned)e / 9u;
        const unsigned c   = (unsigned)e - row * 9u;
        out[e] = g_table[g_idx[row] * 9 + c];
    }
}

// ======================= finalize =======================
__global__ void vq_final_kernel(float* __restrict__ out) {
    __shared__ double red[256];
    const int tid = threadIdx.x;
    double ent = 0.0;
    for (int j = tid; j < 1024; j += 256) {
        double p = (double)g_counts[j] / (double)NROWS;
        ent += p * log(p + 1e-10);
    }
    red[tid] = ent;
    __syncthreads();
    for (int off = 128; off; off >>= 1) {
        if (tid < off) red[tid] += red[tid + off];
        __syncthreads();
    }
    if (tid == 0) {
        out[(size_t)NROWS*9]     = (float)(g_loss * (1.25 / ((double)NROWS * 64.0)));
        out[(size_t)NROWS*9 + 1] = (float)exp(-red[0]);
    }
}

// ======================= launch =======================
extern "C" void kernel_launch(void* const* d_in, const int* in_sizes, int n_in,
                              void* d_out, int out_size) {
    const float* x   = (const float*)d_in[0];
    const float* ew1 = (const float*)d_in[1];
    const float* eb1 = (const float*)d_in[2];
    const float* ew2 = (const float*)d_in[3];
    const float* eb2 = (const float*)d_in[4];
    const float* ew3 = (const float*)d_in[5];
    const float* eb3 = (const float*)d_in[6];
    const float* dw1 = (const float*)d_in[7];
    const float* db1 = (const float*)d_in[8];
    const float* dw2 = (const float*)d_in[9];
    const float* db2 = (const float*)d_in[10];
    const float* dw3 = (const float*)d_in[11];
    const float* db3 = (const float*)d_in[12];
    const float* cbk = (const float*)d_in[13];
    float* out = (float*)d_out;

    static_assert(E_TOTAL * 4 <= 232448, "enc smem");
    static_assert(D_TOTAL * 4 * 3 <= 232448, "dist smem x3");
    static_assert(C_TOTAL * 4 <= 232448, "dectab smem");

    cudaFuncSetAttribute(vq_enc_kernel,    cudaFuncAttributeMaxDynamicSharedMemorySize, E_TOTAL * 4);
    cudaFuncSetAttribute(vq_dist_kernel,   cudaFuncAttributeMaxDynamicSharedMemorySize, D_TOTAL * 4);
    cudaFuncSetAttribute(vq_dectab_kernel, cudaFuncAttributeMaxDynamicSharedMemorySize, C_TOTAL * 4);

    vq_init_kernel<<<4, 256>>>(cbk);
    vq_enc_kernel<<<152, ENT, E_TOTAL * 4>>>(x, ew1, eb1, ew2, eb2, ew3, eb3);
    vq_dist_kernel<<<456, DNT, D_TOTAL * 4>>>(cbk);
    vq_dectab_kernel<<<32, CNT, C_TOTAL * 4>>>(dw1, db1, dw2, db2, dw3, db3, cbk);
    vq_gather_kernel<<<(NROWS*9 + 255)/256, 256>>>(out);
    vq_final_kernel<<<1, 256>>>(out);
}

// round 13
// speedup vs baseline: 1.2884x; 1.2884x over previous
#include <cuda_runtime.h>
#include <math.h>

typedef unsigned long long ull;

#define NROWS 262144

// ---------------- device scratch ----------------
__device__ float  g_cnorm[1024];
__device__ int    g_counts[1024];
__device__ double g_loss;
__device__ float  g_ze[(size_t)NROWS * 64];
__device__ int    g_idx[NROWS];
__device__ float  g_table[1024 * 9];

// ---------------- packed f32x2 helpers ----------------
__device__ __forceinline__ void fma2(ull &d, ull a, ull b) {
    asm("fma.rn.f32x2 %0, %1, %2, %0;" : "+l"(d) : "l"(a), "l"(b));
}
__device__ __forceinline__ ull pk2(float lo, float hi) {
    ull r; asm("mov.b64 %0, {%1, %2};" : "=l"(r) : "f"(lo), "f"(hi)); return r;
}
__device__ __forceinline__ float upk_sum(ull v) {
    float lo, hi; asm("mov.b64 {%0, %1}, %2;" : "=f"(lo), "=f"(hi) : "l"(v));
    return lo + hi;
}

// ======================= init =======================
__global__ void vq_init_kernel(const float* __restrict__ cb) {
    int j = blockIdx.x * blockDim.x + threadIdx.x;
    if (j < 1024) {
        float sum = 0.f;
        #pragma unroll
        for (int k = 0; k < 64; k += 4) {
            float4 v = *reinterpret_cast<const float4*>(&cb[j*64 + k]);
            sum = fmaf(v.x,v.x, fmaf(v.y,v.y, fmaf(v.z,v.z, fmaf(v.w,v.w, sum))));
        }
        g_cnorm[j]  = sum;
        g_counts[j] = 0;
        if (j == 0) g_loss = 0.0;
    }
}

// ======================= encoder (512 threads) =======================
#define E_W2 0
#define E_B2 33280
#define E_W3 33408
#define E_B3 41856
#define E_XS 41920
#define E_H1 42240
#define E_H2 50432
#define E_TOTAL 54656
#define ENT 512

__global__ void __launch_bounds__(ENT, 1) vq_enc_kernel(
    const float* __restrict__ x,
    const float* __restrict__ w1, const float* __restrict__ b1,
    const float* __restrict__ w2, const float* __restrict__ b2,
    const float* __restrict__ w3, const float* __restrict__ b3)
{
    extern __shared__ float s[];
    const int tid = threadIdx.x;

    for (int i = tid; i < 128*256; i += ENT) { int r = i >> 8, c = i & 255; s[E_W2 + r*260 + c] = w2[i]; }
    for (int i = tid; i < 128;     i += ENT) s[E_B2 + i] = b2[i];
    for (int i = tid; i < 64*128;  i += ENT) { int r = i >> 7, c = i & 127; s[E_W3 + r*132 + c] = w3[i]; }
    for (int i = tid; i < 64;      i += ENT) s[E_B3 + i] = b3[i];

    const int col1 = tid & 255;
    const int rp0  = (tid >> 8) * 8;
    ull rw1p[9];
    const float rb1 = __ldg(&b1[col1]);
    #pragma unroll
    for (int k = 0; k < 9; k++) { float w = __ldg(&w1[col1*9 + k]); rw1p[k] = pk2(w, w); }
    __syncthreads();

    const int cp  = tid & 63, rg  = tid >> 6;
    const int cq  = tid & 31, rg3 = tid >> 5;

    for (int tile = blockIdx.x; tile < NROWS/32; tile += gridDim.x) {
        const int row0 = tile * 32;

        if (tid < 288) {
            int r = tid / 9, k = tid - r*9;
            s[E_XS + k*32 + r] = x[(size_t)(row0 + r)*9 + k];
        }
        __syncthreads();

        // L1: 9 -> 256, relu
        #pragma unroll
        for (int j = 0; j < 8; j++) {
            const int rp = rp0 + j;
            ull acc = pk2(rb1, rb1);
            #pragma unroll
            for (int k = 0; k < 9; k++)
                fma2(acc, *reinterpret_cast<const ull*>(&s[E_XS + k*32 + 2*rp]), rw1p[k]);
            float lo, hi; asm("mov.b64 {%0,%1}, %2;" : "=f"(lo), "=f"(hi) : "l"(acc));
            s[E_H1 + (2*rp)  *256 + col1] = fmaxf(lo, 0.f);
            s[E_H1 + (2*rp+1)*256 + col1] = fmaxf(hi, 0.f);
        }
        __syncthreads();

        // L2: 256 -> 128, relu (2 cols x 4 rows)
        {
            ull acc[4][2];
            const float bb0 = s[E_B2 + cp], bb1 = s[E_B2 + cp + 64];
            #pragma unroll
            for (int i = 0; i < 4; i++) { acc[i][0] = pk2(bb0, 0.f); acc[i][1] = pk2(bb1, 0.f); }
            const float* w0p = &s[E_W2 + cp*260];
            const float* w1p = &s[E_W2 + (cp+64)*260];
            const float* hp  = &s[E_H1 + rg*4*256];
            #pragma unroll 4
            for (int k4 = 0; k4 < 256; k4 += 4) {
                ulonglong2 w0  = *reinterpret_cast<const ulonglong2*>(w0p + k4);
                ulonglong2 w1v = *reinterpret_cast<const ulonglong2*>(w1p + k4);
                #pragma unroll
                for (int i = 0; i < 4; i++) {
                    ulonglong2 h = *reinterpret_cast<const ulonglong2*>(hp + i*256 + k4);
                    fma2(acc[i][0], w0.x,  h.x); fma2(acc[i][0], w0.y,  h.y);
                    fma2(acc[i][1], w1v.x, h.x); fma2(acc[i][1], w1v.y, h.y);
                }
            }
            #pragma unroll
            for (int i = 0; i < 4; i++) {
                s[E_H2 + (rg*4+i)*132 + cp]      = fmaxf(upk_sum(acc[i][0]), 0.f);
                s[E_H2 + (rg*4+i)*132 + cp + 64] = fmaxf(upk_sum(acc[i][1]), 0.f);
            }
        }
        __syncthreads();

        // L3: 128 -> 64 (2 cols x 2 rows)
        {
            ull acc[2][2];
            const float bb0 = s[E_B3 + cq], bb1 = s[E_B3 + cq + 32];
            #pragma unroll
            for (int i = 0; i < 2; i++) { acc[i][0] = pk2(bb0, 0.f); acc[i][1] = pk2(bb1, 0.f); }
            const float* w0p = &s[E_W3 + cq*132];
            const float* w1p = &s[E_W3 + (cq+32)*132];
            const float* hp  = &s[E_H2 + rg3*2*132];
            #pragma unroll 4
            for (int k4 = 0; k4 < 128; k4 += 4) {
                ulonglong2 w0  = *reinterpret_cast<const ulonglong2*>(w0p + k4);
                ulonglong2 w1v = *reinterpret_cast<const ulonglong2*>(w1p + k4);
                #pragma unroll
                for (int i = 0; i < 2; i++) {
                    ulonglong2 h = *reinterpret_cast<const ulonglong2*>(hp + i*132 + k4);
                    fma2(acc[i][0], w0.x,  h.x); fma2(acc[i][0], w0.y,  h.y);
                    fma2(acc[i][1], w1v.x, h.x); fma2(acc[i][1], w1v.y, h.y);
                }
            }
            #pragma unroll
            for (int i = 0; i < 2; i++) {
                size_t row = (size_t)(row0 + rg3*2 + i);
                g_ze[row*64 + cq]      = upk_sum(acc[i][0]);
                g_ze[row*64 + cq + 32] = upk_sum(acc[i][1]);
            }
        }
        __syncthreads();
    }
}

// ======================= distance / argmin / loss / hist =======================
// R7 layout; inner loop re-blocked to 2 codes x 8 rows (half accumulators,
// ~30 regs freed for deeper load scheduling), natural 2 CTAs/SM.
#define D_ZS 0
#define D_CB 8704
#define D_SB 17664
#define D_SI 17792
#define D_ZN 17920
#define D_LR 18048
#define D_TOTAL 18056
#define DNT 256

__global__ void __launch_bounds__(DNT, 2) vq_dist_kernel(const float* __restrict__ cb)
{
    extern __shared__ float s[];
    const int tid  = threadIdx.x;
    const int lane = tid & 31, warp = tid >> 5;
    const int r0 = warp * 16;

    for (int st = blockIdx.x; st < NROWS/128; st += gridDim.x) {
        const size_t base = (size_t)st * 128 * 64;

        for (int i = tid; i < 2048; i += DNT) {
            float4 v = *reinterpret_cast<const float4*>(&g_ze[base + (size_t)i*4]);
            int r = i >> 4, c4 = (i & 15) * 4;
            *reinterpret_cast<float4*>(&s[D_ZS + r*68 + c4]) = v;
        }
        __syncthreads();

        if (tid < 128) {
            float zn = 0.f;
            const float* zp = &s[D_ZS + tid*68];
            #pragma unroll
            for (int k = 0; k < 64; k += 4) {
                float4 v = *reinterpret_cast<const float4*>(zp + k);
                zn = fmaf(v.x,v.x, fmaf(v.y,v.y, fmaf(v.z,v.z, fmaf(v.w,v.w, zn))));
            }
            s[D_ZN + tid] = zn;
        }

        float best[16]; int bidx[16];
        #pragma unroll
        for (int i = 0; i < 16; i++) { best[i] = 1e30f; bidx[i] = 0; }
        __syncthreads();

        for (int p = 0; p < 8; p++) {
            const int cbase = p * 128;
            for (int i = tid; i < 2048; i += DNT) {
                int r = i >> 4, q4 = (i & 15) * 4;
                ulonglong2 v = *reinterpret_cast<const ulonglong2*>(&cb[(size_t)(cbase + r)*64 + q4]);
                *reinterpret_cast<ull*>(&s[D_CB + r*70 + q4])     = v.x;
                *reinterpret_cast<ull*>(&s[D_CB + r*70 + q4 + 2]) = v.y;
            }
            if (tid < 128) s[D_CB + tid*70 + 64] = g_cnorm[cbase + tid];
            __syncthreads();

            #pragma unroll 1
            for (int cg = 0; cg < 2; cg++) {
                const int c0 = cg*64 + lane, c1 = c0 + 32;
                const float* b0p = &s[D_CB + c0*70];
                const float* b1p = &s[D_CB + c1*70];
                const float cn0 = b0p[64], cn1 = b1p[64];
                const int j0 = cbase + c0, j1 = cbase + c1;
                #pragma unroll 1
                for (int rp = 0; rp < 2; rp++) {
                    ull acc0[8], acc1[8];
                    #pragma unroll
                    for (int i = 0; i < 8; i++) { acc0[i] = 0ull; acc1[i] = 0ull; }
                    const float* ap = &s[D_ZS + (r0 + rp*8)*68];
                    #pragma unroll 4
                    for (int k4 = 0; k4 < 64; k4 += 4) {
                        // stride-70 rows are only 8B-aligned: must stay ull (8B) loads
                        ull b00 = *reinterpret_cast<const ull*>(b0p + k4);
                        ull b01 = *reinterpret_cast<const ull*>(b0p + k4 + 2);
                        ull b10 = *reinterpret_cast<const ull*>(b1p + k4);
                        ull b11 = *reinterpret_cast<const ull*>(b1p + k4 + 2);
                        #pragma unroll
                        for (int i = 0; i < 8; i++) {
                            ulonglong2 a = *reinterpret_cast<const ulonglong2*>(ap + i*68 + k4);
                            fma2(acc0[i], b00, a.x); fma2(acc0[i], b01, a.y);
                            fma2(acc1[i], b10, a.x); fma2(acc1[i], b11, a.y);
                        }
                    }
                    #pragma unroll
                    for (int i = 0; i < 8; i++) {
                        const int row = rp*8 + i;
                        float d0 = fmaf(-2.f, upk_sum(acc0[i]), cn0);
                        float d1 = fmaf(-2.f, upk_sum(acc1[i]), cn1);
                        // per-lane candidates visited in ascending index order; strict < keeps lowest
                        if (d0 < best[row]) { best[row] = d0; bidx[row] = j0; }
                        if (d1 < best[row]) { best[row] = d1; bidx[row] = j1; }
                    }
                }
            }
            __syncthreads();
        }

        // cross-lane argmin, once per tile (tie-break: smaller index)
        #pragma unroll
        for (int i = 0; i < 16; i++) {
            float v = best[i]; int id = bidx[i];
            #pragma unroll
            for (int off = 16; off; off >>= 1) {
                float ov = __shfl_down_sync(0xffffffffu, v, off);
                int   oi = __shfl_down_sync(0xffffffffu, id, off);
                if (ov < v || (ov == v && oi < id)) { v = ov; id = oi; }
            }
            if (lane == 0) {
                s[D_SB + r0 + i] = v;
                reinterpret_cast<int*>(&s[D_SI])[r0 + i] = id;
            }
        }
        __syncthreads();

        float ll = 0.f;
        if (tid < 128) {
            int id = reinterpret_cast<int*>(&s[D_SI])[tid];
            ll = s[D_SB + tid] + s[D_ZN + tid];
            g_idx[st*128 + tid] = id;
            atomicAdd(&g_counts[id], 1);
        }
        #pragma unroll
        for (int off = 16; off; off >>= 1) ll += __shfl_down_sync(0xffffffffu, ll, off);
        if (lane == 0) s[D_LR + warp] = ll;
        __syncthreads();
        if (tid == 0) {
            float tot = 0.f;
            #pragma unroll
            for (int w = 0; w < 8; w++) tot += s[D_LR + w];
            atomicAdd(&g_loss, (double)tot);
        }
        __syncthreads();
    }
}

// ======================= decoder table: mlp3 over the 1024 codebook rows =======================
#define C_W1  0
#define C_B1  8704
#define C_W2  8832
#define C_B2  42624
#define C_W3  42880
#define C_B3  45220
#define C_S1  45232
#define C_S2  53552
#define C_TOTAL 57808
#define CNT 256

__global__ void __launch_bounds__(CNT, 1) vq_dectab_kernel(
    const float* __restrict__ w1, const float* __restrict__ b1,
    const float* __restrict__ w2, const float* __restrict__ b2,
    const float* __restrict__ w3, const float* __restrict__ b3,
    const float* __restrict__ cb)
{
    extern __shared__ float s[];
    const int tid = threadIdx.x;

    for (int i = tid; i < 128*64;  i += CNT) { int r = i >> 6, c = i & 63;  s[C_W1 + r*68  + c] = w1[i]; }
    for (int i = tid; i < 128;     i += CNT) s[C_B1 + i] = b1[i];
    for (int i = tid; i < 256*128; i += CNT) { int r = i >> 7, c = i & 127; s[C_W2 + r*132 + c] = w2[i]; }
    for (int i = tid; i < 256;     i += CNT) s[C_B2 + i] = b2[i];
    for (int i = tid; i < 9*256;   i += CNT) { int r = i >> 8, c = i & 255; s[C_W3 + r*260 + c] = w3[i]; }
    for (int i = tid; i < 9;       i += CNT) s[C_B3 + i] = b3[i];
    __syncthreads();

    const int cp = tid & 63, rg = tid >> 6;

    for (int tile = blockIdx.x; tile < 1024/32; tile += gridDim.x) {
        const int row0 = tile * 32;

        for (int t = tid; t < 512; t += CNT) {
            int r = t >> 4, j = (t & 15) * 4;
            float4 v = *reinterpret_cast<const float4*>(&cb[(size_t)(row0 + r)*64 + j]);
            *reinterpret_cast<float4*>(&s[C_S1 + r*68 + j]) = v;
        }
        __syncthreads();

        // D1: 64 -> 128, relu (2 cols x 8 rows)
        {
            ull acc[8][2];
            const float bb0 = s[C_B1 + cp], bb1 = s[C_B1 + cp + 64];
            #pragma unroll
            for (int i = 0; i < 8; i++) { acc[i][0] = pk2(bb0, 0.f); acc[i][1] = pk2(bb1, 0.f); }
            const float* w0p = &s[C_W1 + cp*68];
            const float* w1p = &s[C_W1 + (cp+64)*68];
            const float* hp  = &s[C_S1 + rg*8*68];
            #pragma unroll 4
            for (int k4 = 0; k4 < 64; k4 += 4) {
                ulonglong2 w0  = *reinterpret_cast<const ulonglong2*>(w0p + k4);
                ulonglong2 w1v = *reinterpret_cast<const ulonglong2*>(w1p + k4);
                #pragma unroll
                for (int i = 0; i < 8; i++) {
                    ulonglong2 h = *reinterpret_cast<const ulonglong2*>(hp + i*68 + k4);
                    fma2(acc[i][0], w0.x,  h.x); fma2(acc[i][0], w0.y,  h.y);
                    fma2(acc[i][1], w1v.x, h.x); fma2(acc[i][1], w1v.y, h.y);
                }
            }
            #pragma unroll
            for (int i = 0; i < 8; i++) {
                s[C_S2 + (rg*8+i)*132 + cp]      = fmaxf(upk_sum(acc[i][0]), 0.f);
                s[C_S2 + (rg*8+i)*132 + cp + 64] = fmaxf(upk_sum(acc[i][1]), 0.f);
            }
        }
        __syncthreads();

        // D2: 128 -> 256, relu (4 cols x 8 rows)
        {
            ull acc[8][4];
            #pragma unroll
            for (int c = 0; c < 4; c++) {
                const float bb = s[C_B2 + cp + 64*c];
                #pragma unroll
                for (int i = 0; i < 8; i++) acc[i][c] = pk2(bb, 0.f);
            }
            const float* wp0 = &s[C_W2 + cp*132];
            const float* wp1 = &s[C_W2 + (cp+64)*132];
            const float* wp2 = &s[C_W2 + (cp+128)*132];
            const float* wp3 = &s[C_W2 + (cp+192)*132];
            const float* hp  = &s[C_S2 + rg*8*132];
            #pragma unroll 2
            for (int k4 = 0; k4 < 128; k4 += 4) {
                ulonglong2 w0 = *reinterpret_cast<const ulonglong2*>(wp0 + k4);
                ulonglong2 w1 = *reinterpret_cast<const ulonglong2*>(wp1 + k4);
                ulonglong2 w2 = *reinterpret_cast<const ulonglong2*>(wp2 + k4);
                ulonglong2 w3 = *reinterpret_cast<const ulonglong2*>(wp3 + k4);
                #pragma unroll
                for (int i = 0; i < 8; i++) {
                    ulonglong2 h = *reinterpret_cast<const ulonglong2*>(hp + i*132 + k4);
                    fma2(acc[i][0], w0.x, h.x); fma2(acc[i][0], w0.y, h.y);
                    fma2(acc[i][1], w1.x, h.x); fma2(acc[i][1], w1.y, h.y);
                    fma2(acc[i][2], w2.x, h.x); fma2(acc[i][2], w2.y, h.y);
                    fma2(acc[i][3], w3.x, h.x); fma2(acc[i][3], w3.y, h.y);
                }
            }
            #pragma unroll
            for (int i = 0; i < 8; i++)
                #pragma unroll
                for (int c = 0; c < 4; c++)
                    s[C_S1 + (rg*8+i)*260 + cp + 64*c] = fmaxf(upk_sum(acc[i][c]), 0.f);
        }
        __syncthreads();

        // D3: 256 -> 9, to table
        for (int t = tid; t < 288; t += CNT) {
            int r = t / 9, c = t - r*9;
            ull a0 = pk2(s[C_B3 + c], 0.f), a1 = 0ull;
            const float* wp  = &s[C_W3 + c*260];
            const float* hp2 = &s[C_S1 + r*260];
            #pragma unroll 4
            for (int k4 = 0; k4 < 256; k4 += 4) {
                ulonglong2 w = *reinterpret_cast<const ulonglong2*>(wp + k4);
                ulonglong2 h = *reinterpret_cast<const ulonglong2*>(hp2 + k4);
                fma2(a0, w.x, h.x); fma2(a1, w.y, h.y);
            }
            g_table[(row0 + r)*9 + c] = upk_sum(a0) + upk_sum(a1);
        }
        __syncthreads();
    }
}

// ======================= gather: out[i] = table[idx[i]] =======================
__global__ void vq_gather_kernel(float* __restrict__ out) {
    const int e = blockIdx.x * blockDim.x + threadIdx.x;   // over NROWS*9
    if (e < NROWS * 9) {
        const unsigned row = (unsigned)e / 9u;
        const unsigned c   = (unsigned)e - row * 9u;
        out[e] = g_table[g_idx[row] * 9 + c];
    }
}

// ======================= finalize =======================
__global__ void vq_final_kernel(float* __restrict__ out) {
    __shared__ double red[256];
    const int tid = threadIdx.x;
    double ent = 0.0;
    for (int j = tid; j < 1024; j += 256) {
        double p = (double)g_counts[j] / (double)NROWS;
        ent += p * log(p + 1e-10);
    }
    red[tid] = ent;
    __syncthreads();
    for (int off = 128; off; off >>= 1) {
        if (tid < off) red[tid] += red[tid + off];
        __syncthreads();
    }
    if (tid == 0) {
        out[(size_t)NROWS*9]     = (float)(g_loss * (1.25 / ((double)NROWS * 64.0)));
        out[(size_t)NROWS*9 + 1] = (float)exp(-red[0]);
    }
}

// ======================= launch =======================
extern "C" void kernel_launch(void* const* d_in, const int* in_sizes, int n_in,
                              void* d_out, int out_size) {
    const float* x   = (const float*)d_in[0];
    const float* ew1 = (const float*)d_in[1];
    const float* eb1 = (const float*)d_in[2];
    const float* ew2 = (const float*)d_in[3];
    const float* eb2 = (const float*)d_in[4];
    const float* ew3 = (const float*)d_in[5];
    const float* eb3 = (const float*)d_in[6];
    const float* dw1 = (const float*)d_in[7];
    const float* db1 = (const float*)d_in[8];
    const float* dw2 = (const float*)d_in[9];
    const float* db2 = (const float*)d_in[10];
    const float* dw3 = (const float*)d_in[11];
    const float* db3 = (const float*)d_in[12];
    const float* cbk = (const float*)d_in[13];
    float* out = (float*)d_out;

    static_assert(E_TOTAL * 4 <= 232448, "enc smem");
    static_assert(D_TOTAL * 4 * 2 <= 232448, "dist smem x2");
    static_assert(C_TOTAL * 4 <= 232448, "dectab smem");

    cudaFuncSetAttribute(vq_enc_kernel,    cudaFuncAttributeMaxDynamicSharedMemorySize, E_TOTAL * 4);
    cudaFuncSetAttribute(vq_dist_kernel,   cudaFuncAttributeMaxDynamicSharedMemorySize, D_TOTAL * 4);
    cudaFuncSetAttribute(vq_dectab_kernel, cudaFuncAttributeMaxDynamicSharedMemorySize, C_TOTAL * 4);

    vq_init_kernel<<<4, 256>>>(cbk);
    vq_enc_kernel<<<152, ENT, E_TOTAL * 4>>>(x, ew1, eb1, ew2, eb2, ew3, eb3);
    vq_dist_kernel<<<304, DNT, D_TOTAL * 4>>>(cbk);
    vq_dectab_kernel<<<32, CNT, C_TOTAL * 4>>>(dw1, db1, dw2, db2, dw3, db3, cbk);
    vq_gather_kernel<<<(NROWS*9 + 255)/256, 256>>>(out);
    vq_final_kernel<<<1, 256>>>(out);
}

// round 16
// speedup vs baseline: 1.5667x; 1.2160x over previous
#include <cuda_runtime.h>
#include <cstdint>
#include <math.h>

typedef unsigned long long ull;

#define NROWS 262144

// ---------------- device scratch ----------------
__device__ float  g_cnorm[1024];
__device__ int    g_counts[1024];
__device__ double g_loss;
__device__ float  g_ze[(size_t)NROWS * 64];
__device__ int    g_idx[NROWS];
__device__ float  g_table[1024 * 9];
__device__ float  g_cbhi[1024 * 64];
__device__ float  g_cblo[1024 * 64];

// ---------------- packed f32x2 helpers ----------------
__device__ __forceinline__ void fma2(ull &d, ull a, ull b) {
    asm("fma.rn.f32x2 %0, %1, %2, %0;" : "+l"(d) : "l"(a), "l"(b));
}
__device__ __forceinline__ ull pk2(float lo, float hi) {
    ull r; asm("mov.b64 %0, {%1, %2};" : "=l"(r) : "f"(lo), "f"(hi)); return r;
}
__device__ __forceinline__ float upk_sum(ull v) {
    float lo, hi; asm("mov.b64 {%0, %1}, %2;" : "=f"(lo), "=f"(hi) : "l"(v));
    return lo + hi;
}
__device__ __forceinline__ float to_tf32(float v) {
    float r; asm("cvt.rna.tf32.f32 %0, %1;" : "=f"(r) : "f"(v)); return r;
}
// legacy tensor-core mma (sm_80+ PTX, valid on base sm_103 target)
__device__ __forceinline__ void mma8(float* d, uint32_t a0, uint32_t a1, uint32_t a2, uint32_t a3,
                                     uint32_t b0, uint32_t b1) {
    asm volatile("mma.sync.aligned.m16n8k8.row.col.f32.tf32.tf32.f32 "
        "{%0,%1,%2,%3}, {%4,%5,%6,%7}, {%8,%9}, {%0,%1,%2,%3};"
        : "+f"(d[0]), "+f"(d[1]), "+f"(d[2]), "+f"(d[3])
        : "r"(a0), "r"(a1), "r"(a2), "r"(a3), "r"(b0), "r"(b1));
}

// ======================= init: norms, counts, tf32 split codebook =======================
__global__ void vq_init_kernel(const float* __restrict__ cb) {
    int j = blockIdx.x * blockDim.x + threadIdx.x;
    if (j < 1024) {
        float sum = 0.f;
        #pragma unroll
        for (int k = 0; k < 64; k += 4) {
            float4 v = *reinterpret_cast<const float4*>(&cb[j*64 + k]);
            sum = fmaf(v.x,v.x, fmaf(v.y,v.y, fmaf(v.z,v.z, fmaf(v.w,v.w, sum))));
        }
        g_cnorm[j]  = sum;
        g_counts[j] = 0;
        if (j == 0) g_loss = 0.0;
        for (int k = 0; k < 64; k++) {
            float c  = cb[j*64 + k];
            float hi = to_tf32(c);
            float lo = to_tf32(c - hi);
            g_cbhi[j*64 + k] = hi;
            g_cblo[j*64 + k] = lo;
        }
    }
}

// ======================= encoder (512 threads) — unchanged R13 =======================
#define E_W2 0
#define E_B2 33280
#define E_W3 33408
#define E_B3 41856
#define E_XS 41920
#define E_H1 42240
#define E_H2 50432
#define E_TOTAL 54656
#define ENT 512

__global__ void __launch_bounds__(ENT, 1) vq_enc_kernel(
    const float* __restrict__ x,
    const float* __restrict__ w1, const float* __restrict__ b1,
    const float* __restrict__ w2, const float* __restrict__ b2,
    const float* __restrict__ w3, const float* __restrict__ b3)
{
    extern __shared__ float s[];
    const int tid = threadIdx.x;

    for (int i = tid; i < 128*256; i += ENT) { int r = i >> 8, c = i & 255; s[E_W2 + r*260 + c] = w2[i]; }
    for (int i = tid; i < 128;     i += ENT) s[E_B2 + i] = b2[i];
    for (int i = tid; i < 64*128;  i += ENT) { int r = i >> 7, c = i & 127; s[E_W3 + r*132 + c] = w3[i]; }
    for (int i = tid; i < 64;      i += ENT) s[E_B3 + i] = b3[i];

    const int col1 = tid & 255;
    const int rp0  = (tid >> 8) * 8;
    ull rw1p[9];
    const float rb1 = __ldg(&b1[col1]);
    #pragma unroll
    for (int k = 0; k < 9; k++) { float w = __ldg(&w1[col1*9 + k]); rw1p[k] = pk2(w, w); }
    __syncthreads();

    const int cp  = tid & 63, rg  = tid >> 6;
    const int cq  = tid & 31, rg3 = tid >> 5;

    for (int tile = blockIdx.x; tile < NROWS/32; tile += gridDim.x) {
        const int row0 = tile * 32;

        if (tid < 288) {
            int r = tid / 9, k = tid - r*9;
            s[E_XS + k*32 + r] = x[(size_t)(row0 + r)*9 + k];
        }
        __syncthreads();

        #pragma unroll
        for (int j = 0; j < 8; j++) {
            const int rp = rp0 + j;
            ull acc = pk2(rb1, rb1);
            #pragma unroll
            for (int k = 0; k < 9; k++)
                fma2(acc, *reinterpret_cast<const ull*>(&s[E_XS + k*32 + 2*rp]), rw1p[k]);
            float lo, hi; asm("mov.b64 {%0,%1}, %2;" : "=f"(lo), "=f"(hi) : "l"(acc));
            s[E_H1 + (2*rp)  *256 + col1] = fmaxf(lo, 0.f);
            s[E_H1 + (2*rp+1)*256 + col1] = fmaxf(hi, 0.f);
        }
        __syncthreads();

        {
            ull acc[4][2];
            const float bb0 = s[E_B2 + cp], bb1 = s[E_B2 + cp + 64];
            #pragma unroll
            for (int i = 0; i < 4; i++) { acc[i][0] = pk2(bb0, 0.f); acc[i][1] = pk2(bb1, 0.f); }
            const float* w0p = &s[E_W2 + cp*260];
            const float* w1p = &s[E_W2 + (cp+64)*260];
            const float* hp  = &s[E_H1 + rg*4*256];
            #pragma unroll 4
            for (int k4 = 0; k4 < 256; k4 += 4) {
                ulonglong2 w0  = *reinterpret_cast<const ulonglong2*>(w0p + k4);
                ulonglong2 w1v = *reinterpret_cast<const ulonglong2*>(w1p + k4);
                #pragma unroll
                for (int i = 0; i < 4; i++) {
                    ulonglong2 h = *reinterpret_cast<const ulonglong2*>(hp + i*256 + k4);
                    fma2(acc[i][0], w0.x,  h.x); fma2(acc[i][0], w0.y,  h.y);
                    fma2(acc[i][1], w1v.x, h.x); fma2(acc[i][1], w1v.y, h.y);
                }
            }
            #pragma unroll
            for (int i = 0; i < 4; i++) {
                s[E_H2 + (rg*4+i)*132 + cp]      = fmaxf(upk_sum(acc[i][0]), 0.f);
                s[E_H2 + (rg*4+i)*132 + cp + 64] = fmaxf(upk_sum(acc[i][1]), 0.f);
            }
        }
        __syncthreads();

        {
            ull acc[2][2];
            const float bb0 = s[E_B3 + cq], bb1 = s[E_B3 + cq + 32];
            #pragma unroll
            for (int i = 0; i < 2; i++) { acc[i][0] = pk2(bb0, 0.f); acc[i][1] = pk2(bb1, 0.f); }
            const float* w0p = &s[E_W3 + cq*132];
            const float* w1p = &s[E_W3 + (cq+32)*132];
            const float* hp  = &s[E_H2 + rg3*2*132];
            #pragma unroll 4
            for (int k4 = 0; k4 < 128; k4 += 4) {
                ulonglong2 w0  = *reinterpret_cast<const ulonglong2*>(w0p + k4);
                ulonglong2 w1v = *reinterpret_cast<const ulonglong2*>(w1p + k4);
                #pragma unroll
                for (int i = 0; i < 2; i++) {
                    ulonglong2 h = *reinterpret_cast<const ulonglong2*>(hp + i*132 + k4);
                    fma2(acc[i][0], w0.x,  h.x); fma2(acc[i][0], w0.y,  h.y);
                    fma2(acc[i][1], w1v.x, h.x); fma2(acc[i][1], w1v.y, h.y);
                }
            }
            #pragma unroll
            for (int i = 0; i < 2; i++) {
                size_t row = (size_t)(row0 + rg3*2 + i);
                g_ze[row*64 + cq]      = upk_sum(acc[i][0]);
                g_ze[row*64 + cq + 32] = upk_sum(acc[i][1]);
            }
        }
        __syncthreads();
    }
}

// ======================= distance via mma.sync tf32 split =======================
// 512 threads: warps 0-7 rows (wid*16..+15) x cols 0-63; warps 8-15 same rows x cols 64-127.
#define T_ZS 0          // 128 x 68 fp32 z (for zn)
#define T_AH 8704       // zhi  [128][68]
#define T_AL 17408      // zlo
#define T_BH 26112      // cbhi tile [128][68]
#define T_BL 34816      // cblo tile
#define T_CN 43520      // 128
#define T_ZN 43648      // 128
#define T_SB 43776      // 128
#define T_SI 43904      // 128
#define T_LR 44032      // 8
#define T_TOTAL 44040
#define DNT 512

__global__ void __launch_bounds__(DNT, 1) vq_dist_kernel()
{
    extern __shared__ float s[];
    uint32_t* su = reinterpret_cast<uint32_t*>(s);
    const int tid  = threadIdx.x;
    const int lane = tid & 31, wid = tid >> 5;
    const int r4 = lane >> 2, c4 = lane & 3;
    const int rowbase = (wid & 7) * 16;
    const int colhalf = (wid >> 3) * 64;

    for (int st = blockIdx.x; st < NROWS/128; st += gridDim.x) {
        const size_t base = (size_t)st * 128 * 64;

        // stage z (fp32 for norms) + tf32 hi/lo operand tiles
        for (int i = tid; i < 2048; i += DNT) {
            float4 v = *reinterpret_cast<const float4*>(&g_ze[base + (size_t)i*4]);
            int r = i >> 4, k4 = (i & 15) * 4;
            *reinterpret_cast<float4*>(&s[T_ZS + r*68 + k4]) = v;
            float4 hi, lo;
            hi.x = to_tf32(v.x); lo.x = to_tf32(v.x - hi.x);
            hi.y = to_tf32(v.y); lo.y = to_tf32(v.y - hi.y);
            hi.z = to_tf32(v.z); lo.z = to_tf32(v.z - hi.z);
            hi.w = to_tf32(v.w); lo.w = to_tf32(v.w - hi.w);
            *reinterpret_cast<float4*>(&s[T_AH + r*68 + k4]) = hi;
            *reinterpret_cast<float4*>(&s[T_AL + r*68 + k4]) = lo;
        }
        __syncthreads();

        if (tid < 128) {
            float zn = 0.f;
            const float* zp = &s[T_ZS + tid*68];
            #pragma unroll
            for (int k = 0; k < 64; k += 4) {
                float4 v = *reinterpret_cast<const float4*>(zp + k);
                zn = fmaf(v.x,v.x, fmaf(v.y,v.y, fmaf(v.z,v.z, fmaf(v.w,v.w, zn))));
            }
            s[T_ZN + tid] = zn;
        }

        float bw0 = 1e30f, bw1 = 1e30f; int bi0 = 0, bi1 = 0;

        for (int p = 0; p < 8; p++) {
            const int cbase = p * 128;
            __syncthreads();   // previous pass readers done before restage
            for (int i = tid; i < 2048; i += DNT) {
                int r = i >> 4, k4 = (i & 15) * 4;
                float4 vh = *reinterpret_cast<const float4*>(&g_cbhi[(size_t)(cbase + r)*64 + k4]);
                float4 vl = *reinterpret_cast<const float4*>(&g_cblo[(size_t)(cbase + r)*64 + k4]);
                *reinterpret_cast<float4*>(&s[T_BH + r*68 + k4]) = vh;
                *reinterpret_cast<float4*>(&s[T_BL + r*68 + k4]) = vl;
            }
            if (tid < 128) s[T_CN + tid] = g_cnorm[cbase + tid];
            __syncthreads();

            float d[8][4];
            #pragma unroll
            for (int n = 0; n < 8; n++)
                #pragma unroll
                for (int q = 0; q < 4; q++) d[n][q] = 0.f;

            #pragma unroll
            for (int k = 0; k < 8; k++) {
                const int ao = (rowbase + r4)*68 + k*8 + c4;
                uint32_t ah0 = su[T_AH + ao],         ah1 = su[T_AH + ao + 8*68];
                uint32_t ah2 = su[T_AH + ao + 4],     ah3 = su[T_AH + ao + 8*68 + 4];
                uint32_t al0 = su[T_AL + ao],         al1 = su[T_AL + ao + 8*68];
                uint32_t al2 = su[T_AL + ao + 4],     al3 = su[T_AL + ao + 8*68 + 4];
                #pragma unroll
                for (int n = 0; n < 8; n++) {
                    const int bo = (colhalf + n*8 + r4)*68 + k*8 + c4;
                    uint32_t bh0 = su[T_BH + bo], bh1 = su[T_BH + bo + 4];
                    uint32_t bl0 = su[T_BL + bo], bl1 = su[T_BL + bo + 4];
                    mma8(d[n], ah0, ah1, ah2, ah3, bh0, bh1);   // hh
                    mma8(d[n], ah0, ah1, ah2, ah3, bl0, bl1);   // hl
                    mma8(d[n], al0, al1, al2, al3, bh0, bh1);   // lh
                }
            }

            // epilogue: dist = cnorm - 2*dot; running argmin (ascending col order)
            #pragma unroll
            for (int n = 0; n < 8; n++) {
                const int cc = colhalf + n*8 + 2*c4;
                const float cn0 = s[T_CN + cc], cn1 = s[T_CN + cc + 1];
                const int j = cbase + cc;
                float v00 = fmaf(-2.f, d[n][0], cn0);
                float v01 = fmaf(-2.f, d[n][1], cn1);
                float v10 = fmaf(-2.f, d[n][2], cn0);
                float v11 = fmaf(-2.f, d[n][3], cn1);
                if (v00 < bw0) { bw0 = v00; bi0 = j; }
                if (v01 < bw0) { bw0 = v01; bi0 = j + 1; }
                if (v10 < bw1) { bw1 = v10; bi1 = j; }
                if (v11 < bw1) { bw1 = v11; bi1 = j + 1; }
            }
        }

        // reduce within 4-lane groups (same rows, disjoint cols; tie-break smaller idx)
        #pragma unroll
        for (int off = 1; off <= 2; off <<= 1) {
            float o0 = __shfl_xor_sync(0xffffffffu, bw0, off);
            int   i0 = __shfl_xor_sync(0xffffffffu, bi0, off);
            if (o0 < bw0 || (o0 == bw0 && i0 < bi0)) { bw0 = o0; bi0 = i0; }
            float o1 = __shfl_xor_sync(0xffffffffu, bw1, off);
            int   i1 = __shfl_xor_sync(0xffffffffu, bi1, off);
            if (o1 < bw1 || (o1 == bw1 && i1 < bi1)) { bw1 = o1; bi1 = i1; }
        }

        __syncthreads();
        if (colhalf == 0 && c4 == 0) {
            s[T_SB + rowbase + r4]     = bw0;
            s[T_SB + rowbase + 8 + r4] = bw1;
            reinterpret_cast<int*>(&s[T_SI])[rowbase + r4]     = bi0;
            reinterpret_cast<int*>(&s[T_SI])[rowbase + 8 + r4] = bi1;
        }
        __syncthreads();

        float ll = 0.f;
        if (colhalf == 64 && c4 == 0) {
            const int rA = rowbase + r4, rB = rowbase + 8 + r4;
            float oA = s[T_SB + rA]; int iA = reinterpret_cast<int*>(&s[T_SI])[rA];
            if (bw0 < oA || (bw0 == oA && bi0 < iA)) { oA = bw0; iA = bi0; }
            float oB = s[T_SB + rB]; int iB = reinterpret_cast<int*>(&s[T_SI])[rB];
            if (bw1 < oB || (bw1 == oB && bi1 < iB)) { oB = bw1; iB = bi1; }
            g_idx[st*128 + rA] = iA;
            g_idx[st*128 + rB] = iB;
            atomicAdd(&g_counts[iA], 1);
            atomicAdd(&g_counts[iB], 1);
            ll = (oA + s[T_ZN + rA]) + (oB + s[T_ZN + rB]);
        }
        #pragma unroll
        for (int off = 16; off; off >>= 1) ll += __shfl_down_sync(0xffffffffu, ll, off);
        if (colhalf == 64 && lane == 0) s[T_LR + (wid - 8)] = ll;
        __syncthreads();
        if (tid == 0) {
            float tot = 0.f;
            #pragma unroll
            for (int w = 0; w < 8; w++) tot += s[T_LR + w];
            atomicAdd(&g_loss, (double)tot);
        }
        __syncthreads();
    }
}

// ======================= decoder table — unchanged R13 =======================
#define C_W1  0
#define C_B1  8704
#define C_W2  8832
#define C_B2  42624
#define C_W3  42880
#define C_B3  45220
#define C_S1  45232
#define C_S2  53552
#define C_TOTAL 57808
#define CNT 256

__global__ void __launch_bounds__(CNT, 1) vq_dectab_kernel(
    const float* __restrict__ w1, const float* __restrict__ b1,
    const float* __restrict__ w2, const float* __restrict__ b2,
    const float* __restrict__ w3, const float* __restrict__ b3,
    const float* __restrict__ cb)
{
    extern __shared__ float s[];
    const int tid = threadIdx.x;

    for (int i = tid; i < 128*64;  i += CNT) { int r = i >> 6, c = i & 63;  s[C_W1 + r*68  + c] = w1[i]; }
    for (int i = tid; i < 128;     i += CNT) s[C_B1 + i] = b1[i];
    for (int i = tid; i < 256*128; i += CNT) { int r = i >> 7, c = i & 127; s[C_W2 + r*132 + c] = w2[i]; }
    for (int i = tid; i < 256;     i += CNT) s[C_B2 + i] = b2[i];
    for (int i = tid; i < 9*256;   i += CNT) { int r = i >> 8, c = i & 255; s[C_W3 + r*260 + c] = w3[i]; }
    for (int i = tid; i < 9;       i += CNT) s[C_B3 + i] = b3[i];
    __syncthreads();

    const int cp = tid & 63, rg = tid >> 6;

    for (int tile = blockIdx.x; tile < 1024/32; tile += gridDim.x) {
        const int row0 = tile * 32;

        for (int t = tid; t < 512; t += CNT) {
            int r = t >> 4, j = (t & 15) * 4;
            float4 v = *reinterpret_cast<const float4*>(&cb[(size_t)(row0 + r)*64 + j]);
            *reinterpret_cast<float4*>(&s[C_S1 + r*68 + j]) = v;
        }
        __syncthreads();

        {
            ull acc[8][2];
            const float bb0 = s[C_B1 + cp], bb1 = s[C_B1 + cp + 64];
            #pragma unroll
            for (int i = 0; i < 8; i++) { acc[i][0] = pk2(bb0, 0.f); acc[i][1] = pk2(bb1, 0.f); }
            const float* w0p = &s[C_W1 + cp*68];
            const float* w1p = &s[C_W1 + (cp+64)*68];
            const float* hp  = &s[C_S1 + rg*8*68];
            #pragma unroll 4
            for (int k4 = 0; k4 < 64; k4 += 4) {
                ulonglong2 w0  = *reinterpret_cast<const ulonglong2*>(w0p + k4);
                ulonglong2 w1v = *reinterpret_cast<const ulonglong2*>(w1p + k4);
                #pragma unroll
                for (int i = 0; i < 8; i++) {
                    ulonglong2 h = *reinterpret_cast<const ulonglong2*>(hp + i*68 + k4);
                    fma2(acc[i][0], w0.x,  h.x); fma2(acc[i][0], w0.y,  h.y);
                    fma2(acc[i][1], w1v.x, h.x); fma2(acc[i][1], w1v.y, h.y);
                }
            }
            #pragma unroll
            for (int i = 0; i < 8; i++) {
                s[C_S2 + (rg*8+i)*132 + cp]      = fmaxf(upk_sum(acc[i][0]), 0.f);
                s[C_S2 + (rg*8+i)*132 + cp + 64] = fmaxf(upk_sum(acc[i][1]), 0.f);
            }
        }
        __syncthreads();

        {
            ull acc[8][4];
            #pragma unroll
            for (int c = 0; c < 4; c++) {
                const float bb = s[C_B2 + cp + 64*c];
                #pragma unroll
                for (int i = 0; i < 8; i++) acc[i][c] = pk2(bb, 0.f);
            }
            const float* wp0 = &s[C_W2 + cp*132];
            const float* wp1 = &s[C_W2 + (cp+64)*132];
            const float* wp2 = &s[C_W2 + (cp+128)*132];
            const float* wp3 = &s[C_W2 + (cp+192)*132];
            const float* hp  = &s[C_S2 + rg*8*132];
            #pragma unroll 2
            for (int k4 = 0; k4 < 128; k4 += 4) {
                ulonglong2 w0 = *reinterpret_cast<const ulonglong2*>(wp0 + k4);
                ulonglong2 w1 = *reinterpret_cast<const ulonglong2*>(wp1 + k4);
                ulonglong2 w2 = *reinterpret_cast<const ulonglong2*>(wp2 + k4);
                ulonglong2 w3 = *reinterpret_cast<const ulonglong2*>(wp3 + k4);
                #pragma unroll
                for (int i = 0; i < 8; i++) {
                    ulonglong2 h = *reinterpret_cast<const ulonglong2*>(hp + i*132 + k4);
                    fma2(acc[i][0], w0.x, h.x); fma2(acc[i][0], w0.y, h.y);
                    fma2(acc[i][1], w1.x, h.x); fma2(acc[i][1], w1.y, h.y);
                    fma2(acc[i][2], w2.x, h.x); fma2(acc[i][2], w2.y, h.y);
                    fma2(acc[i][3], w3.x, h.x); fma2(acc[i][3], w3.y, h.y);
                }
            }
            #pragma unroll
            for (int i = 0; i < 8; i++)
                #pragma unroll
                for (int c = 0; c < 4; c++)
                    s[C_S1 + (rg*8+i)*260 + cp + 64*c] = fmaxf(upk_sum(acc[i][c]), 0.f);
        }
        __syncthreads();

        for (int t = tid; t < 288; t += CNT) {
            int r = t / 9, c = t - r*9;
            ull a0 = pk2(s[C_B3 + c], 0.f), a1 = 0ull;
            const float* wp  = &s[C_W3 + c*260];
            const float* hp2 = &s[C_S1 + r*260];
            #pragma unroll 4
            for (int k4 = 0; k4 < 256; k4 += 4) {
                ulonglong2 w = *reinterpret_cast<const ulonglong2*>(wp + k4);
                ulonglong2 h = *reinterpret_cast<const ulonglong2*>(hp2 + k4);
                fma2(a0, w.x, h.x); fma2(a1, w.y, h.y);
            }
            g_table[(row0 + r)*9 + c] = upk_sum(a0) + upk_sum(a1);
        }
        __syncthreads();
    }
}

// ======================= gather =======================
__global__ void vq_gather_kernel(float* __restrict__ out) {
    const int e = blockIdx.x * blockDim.x + threadIdx.x;
    if (e < NROWS * 9) {
        const unsigned row = (unsigned)e / 9u;
        const unsigned c   = (unsigned)e - row * 9u;
        out[e] = g_table[g_idx[row] * 9 + c];
    }
}

// ======================= finalize =======================
__global__ void vq_final_kernel(float* __restrict__ out) {
    __shared__ double red[256];
    const int tid = threadIdx.x;
    double ent = 0.0;
    for (int j = tid; j < 1024; j += 256) {
        double p = (double)g_counts[j] / (double)NROWS;
        ent += p * log(p + 1e-10);
    }
    red[tid] = ent;
    __syncthreads();
    for (int off = 128; off; off >>= 1) {
        if (tid < off) red[tid] += red[tid + off];
        __syncthreads();
    }
    if (tid == 0) {
        out[(size_t)NROWS*9]     = (float)(g_loss * (1.25 / ((double)NROWS * 64.0)));
        out[(size_t)NROWS*9 + 1] = (float)exp(-red[0]);
    }
}

// ======================= launch =======================
extern "C" void kernel_launch(void* const* d_in, const int* in_sizes, int n_in,
                              void* d_out, int out_size) {
    const float* x   = (const float*)d_in[0];
    const float* ew1 = (const float*)d_in[1];
    const float* eb1 = (const float*)d_in[2];
    const float* ew2 = (const float*)d_in[3];
    const float* eb2 = (const float*)d_in[4];
    const float* ew3 = (const float*)d_in[5];
    const float* eb3 = (const float*)d_in[6];
    const float* dw1 = (const float*)d_in[7];
    const float* db1 = (const float*)d_in[8];
    const float* dw2 = (const float*)d_in[9];
    const float* db2 = (const float*)d_in[10];
    const float* dw3 = (const float*)d_in[11];
    const float* db3 = (const float*)d_in[12];
    const float* cbk = (const float*)d_in[13];
    float* out = (float*)d_out;

    static_assert(E_TOTAL * 4 <= 232448, "enc smem");
    static_assert(T_TOTAL * 4 <= 232448, "dist smem");
    static_assert(C_TOTAL * 4 <= 232448, "dectab smem");

    cudaFuncSetAttribute(vq_enc_kernel,    cudaFuncAttributeMaxDynamicSharedMemorySize, E_TOTAL * 4);
    cudaFuncSetAttribute(vq_dist_kernel,   cudaFuncAttributeMaxDynamicSharedMemorySize, T_TOTAL * 4);
    cudaFuncSetAttribute(vq_dectab_kernel, cudaFuncAttributeMaxDynamicSharedMemorySize, C_TOTAL * 4);

    vq_init_kernel<<<4, 256>>>(cbk);
    vq_enc_kernel<<<152, ENT, E_TOTAL * 4>>>(x, ew1, eb1, ew2, eb2, ew3, eb3);
    vq_dist_kernel<<<152, DNT, T_TOTAL * 4>>>();
    vq_dectab_kernel<<<32, CNT, C_TOTAL * 4>>>(dw1, db1, dw2, db2, dw3, db3, cbk);
    vq_gather_kernel<<<(NROWS*9 + 255)/256, 256>>>(out);
    vq_final_kernel<<<1, 256>>>(out);
}